// round 1
// baseline (speedup 1.0000x reference)
#include <cuda_runtime.h>
#include <cuda_bf16.h>

#define BATCHN 65536
#define TPB 256

// Apply RY(theta) on the qubit whose bit value is STRIDE (8,4,2,1).
// new0 = c*a - s*b ; new1 = s*a + c*b  (PennyLane RY convention, real state)
template<int STRIDE>
__device__ __forceinline__ void ry_gate(float st[16], float c, float s) {
#pragma unroll
    for (int i = 0; i < 16; i++) {
        if ((i & STRIDE) == 0) {
            float a = st[i];
            float b = st[i | STRIDE];
            st[i]          = c * a - s * b;
            st[i | STRIDE] = s * a + c * b;
        }
    }
}

__device__ __forceinline__ void swp(float &a, float &b) { float t = a; a = b; b = t; }

__global__ __launch_bounds__(TPB)
void dqn_fused_kernel(const float* __restrict__ input,   // [65536, 512]
                      const float* __restrict__ Wpre,    // [4, 512]
                      const float* __restrict__ bpre,    // [4]
                      const float* __restrict__ qparams, // [24]
                      const float* __restrict__ Wpost,   // [200, 4]
                      const float* __restrict__ bpost,   // [200]
                      float* __restrict__ out)           // [65536, 200]
{
    __shared__ float4 sWpre4[512];    // [c][q] : weights for column c across the 4 outputs
    __shared__ float4 sWpost4[200];   // [c][q] : row c of W_post (already contiguous in gmem)
    __shared__ float  sBpost[200];
    __shared__ float  sBpre[4];
    __shared__ float  sQc[24], sQs[24];

    const int tid = threadIdx.x;

    // ---- stage weights in shared (one-time, tiny) ----
    {
        float* sWpre = (float*)sWpre4;
        for (int idx = tid; idx < 2048; idx += TPB) {
            int q = idx >> 9;          // row of W_pre
            int c = idx & 511;         // column
            sWpre[c * 4 + q] = Wpre[idx];   // transpose to [c][q]
        }
        float* sWpostf = (float*)sWpost4;
        for (int idx = tid; idx < 800; idx += TPB) sWpostf[idx] = Wpost[idx];
        for (int idx = tid; idx < 200; idx += TPB) sBpost[idx] = bpost[idx];
        if (tid < 4) sBpre[tid] = bpre[tid];
        if (tid < 24) {
            float a = 0.5f * qparams[tid];
            sQc[tid] = cosf(a);
            sQs[tid] = sinf(a);
        }
    }
    __syncthreads();

    const int s = blockIdx.x * TPB + tid;   // one sample per thread

    // ---- pre-layer: pre_out[q] = input[s,:] . Wpre[q,:] + bpre[q] ----
    const float4* row = (const float4*)(input + (size_t)s * 512);
    float ax = 0.f, ay = 0.f, az = 0.f, aw = 0.f;
#pragma unroll 4
    for (int j = 0; j < 128; j++) {
        float4 x  = row[j];
        float4 w0 = sWpre4[4 * j + 0];
        float4 w1 = sWpre4[4 * j + 1];
        float4 w2 = sWpre4[4 * j + 2];
        float4 w3 = sWpre4[4 * j + 3];
        ax += x.x * w0.x + x.y * w1.x + x.z * w2.x + x.w * w3.x;
        ay += x.x * w0.y + x.y * w1.y + x.z * w2.y + x.w * w3.y;
        az += x.x * w0.z + x.y * w1.z + x.z * w2.z + x.w * w3.z;
        aw += x.x * w0.w + x.y * w1.w + x.z * w2.w + x.w * w3.w;
    }

    // q_in = tanh(pre_out) * pi/2 ; gates use half-angle -> tanh(pre)*pi/4
    const float QPI4 = 0.78539816339744830962f;
    float c0, s0, c1, s1, c2, s2, c3, s3;
    sincosf(tanhf(ax + sBpre[0]) * QPI4, &s0, &c0);
    sincosf(tanhf(ay + sBpre[1]) * QPI4, &s1, &c1);
    sincosf(tanhf(az + sBpre[2]) * QPI4, &s2, &c2);
    sincosf(tanhf(aw + sBpre[3]) * QPI4, &s3, &c3);

    // ---- quantum circuit on 16 register-resident amplitudes ----
    // index i = b0*8 + b1*4 + b2*2 + b3 (qubit q <-> bit value 8>>q)
    float st[16];
#pragma unroll
    for (int i = 0; i < 16; i++) st[i] = 0.25f;

    ry_gate<8>(st, c0, s0);
    ry_gate<4>(st, c1, s1);
    ry_gate<2>(st, c2, s2);
    ry_gate<1>(st, c3, s3);

#pragma unroll
    for (int k = 0; k < 6; k++) {
        // CNOT(0,1): ctrl bit 8, tgt bit 4
        swp(st[8], st[12]); swp(st[9], st[13]); swp(st[10], st[14]); swp(st[11], st[15]);
        // CNOT(2,3): ctrl bit 2, tgt bit 1
        swp(st[2], st[3]); swp(st[6], st[7]); swp(st[10], st[11]); swp(st[14], st[15]);
        // CNOT(1,2): ctrl bit 4, tgt bit 2
        swp(st[4], st[6]); swp(st[5], st[7]); swp(st[12], st[14]); swp(st[13], st[15]);

        ry_gate<8>(st, sQc[4 * k + 0], sQs[4 * k + 0]);
        ry_gate<4>(st, sQc[4 * k + 1], sQs[4 * k + 1]);
        ry_gate<2>(st, sQc[4 * k + 2], sQs[4 * k + 2]);
        ry_gate<1>(st, sQc[4 * k + 3], sQs[4 * k + 3]);
    }

    // ---- measurement: z_q = sum_{bit_q=0} p_i - sum_{bit_q=1} p_i ----
    float z0 = 0.f, z1 = 0.f, z2 = 0.f, z3 = 0.f;
#pragma unroll
    for (int i = 0; i < 16; i++) {
        float p = st[i] * st[i];
        z0 += (i & 8) ? -p : p;
        z1 += (i & 4) ? -p : p;
        z2 += (i & 2) ? -p : p;
        z3 += (i & 1) ? -p : p;
    }

    // ---- post-layer: out[s,c] = bpost[c] + sum_q z_q * Wpost[c][q] ----
    float4* orow4 = (float4*)(out + (size_t)s * 200);
#pragma unroll 2
    for (int jc = 0; jc < 50; jc++) {
        int c = 4 * jc;
        float4 wa = sWpost4[c + 0];
        float4 wb = sWpost4[c + 1];
        float4 wc = sWpost4[c + 2];
        float4 wd = sWpost4[c + 3];
        float4 o;
        o.x = sBpost[c + 0] + z0 * wa.x + z1 * wa.y + z2 * wa.z + z3 * wa.w;
        o.y = sBpost[c + 1] + z0 * wb.x + z1 * wb.y + z2 * wb.z + z3 * wb.w;
        o.z = sBpost[c + 2] + z0 * wc.x + z1 * wc.y + z2 * wc.z + z3 * wc.w;
        o.w = sBpost[c + 3] + z0 * wd.x + z1 * wd.y + z2 * wd.z + z3 * wd.w;
        orow4[jc] = o;
    }
}

extern "C" void kernel_launch(void* const* d_in, const int* in_sizes, int n_in,
                              void* d_out, int out_size)
{
    const float* input   = (const float*)d_in[0];  // [65536,512]
    const float* Wpre    = (const float*)d_in[1];  // [4,512]
    const float* bpre    = (const float*)d_in[2];  // [4]
    const float* qparams = (const float*)d_in[3];  // [24]
    const float* Wpost   = (const float*)d_in[4];  // [200,4]
    const float* bpost   = (const float*)d_in[5];  // [200]
    float* out = (float*)d_out;                    // [65536,200]

    dqn_fused_kernel<<<BATCHN / TPB, TPB>>>(input, Wpre, bpre, qparams, Wpost, bpost, out);
}

// round 2
// speedup vs baseline: 1.5374x; 1.5374x over previous
#include <cuda_runtime.h>
#include <cuda_bf16.h>

#define TPB 256
#define SPB 256            // samples per block
#define NBLK 256           // 65536 / 256
#define CCH 32             // columns per chunk
#define NCH 16             // 512 / 32
#define RSTR 36            // floats per staged row (32 + 4 pad, 144B, keeps 16B align, conflict-free)
#define TILE_F (SPB * RSTR)   // floats per tile buffer

// dynamic smem layout (bytes):
//   [0,                73728)  in-tile double buffer: 2 * 256 * 36 * 4
//   [73728,            81920)  sWpre4: 512 float4  ([col][q] transposed W_pre)
//   [81920,            86016)  szl4:   256 float4  (per-sample z)
//   [86016,            86112)  sQc[24]
//   [86112,            86208)  sQs[24]
//   [86208,            86224)  sBpre[4]
#define SMEM_BYTES 86272

__device__ __forceinline__ unsigned smem_u32(const void* p) {
    return (unsigned)__cvta_generic_to_shared(p);
}

template<int STRIDE>
__device__ __forceinline__ void ry_gate(float st[16], float c, float s) {
#pragma unroll
    for (int i = 0; i < 16; i++) {
        if ((i & STRIDE) == 0) {
            float a = st[i];
            float b = st[i | STRIDE];
            st[i]          = c * a - s * b;
            st[i | STRIDE] = s * a + c * b;
        }
    }
}

__device__ __forceinline__ void swp(float &a, float &b) { float t = a; a = b; b = t; }

// Stage one 256x32 column chunk, coalesced: per warp each LDGSTS covers
// 4 rows x 128B contiguous = 4 cache lines (4 wavefronts).
__device__ __forceinline__ void issue_chunk(float* smbuf, const float* gbase, int ct, int t) {
    const int c4 = t & 7;        // float4 index within chunk row
    const int rb = t >> 3;       // base row
    const float* g = gbase + ct * CCH + c4 * 4;
#pragma unroll
    for (int l = 0; l < 8; l++) {
        int row = l * 32 + rb;
        unsigned sa = smem_u32(smbuf + row * RSTR + c4 * 4);
        asm volatile("cp.async.cg.shared.global [%0], [%1], 16;\n"
                     :: "r"(sa), "l"(g + (size_t)row * 512));
    }
    asm volatile("cp.async.commit_group;\n");
}

__global__ __launch_bounds__(TPB, 2)
void dqn_fused_kernel(const float* __restrict__ input,   // [65536, 512]
                      const float* __restrict__ Wpre,    // [4, 512]
                      const float* __restrict__ bpre,    // [4]
                      const float* __restrict__ qparams, // [24]
                      const float* __restrict__ Wpost,   // [200, 4]
                      const float* __restrict__ bpost,   // [200]
                      float* __restrict__ out)           // [65536, 200]
{
    extern __shared__ float sm[];
    float*  sm_in   = sm;                                   // 2 tile buffers
    float4* sWpre4  = (float4*)(sm + 2 * TILE_F);           // 512 float4
    float4* szl4    = (float4*)(sm + 2 * TILE_F + 2048);    // 256 float4
    float*  sQc     = sm + 2 * TILE_F + 2048 + 1024;
    float*  sQs     = sQc + 24;
    float*  sBpre   = sQs + 24;

    const int t = threadIdx.x;
    const int blockBase = blockIdx.x * SPB;
    const float* gbase = input + (size_t)blockBase * 512;

    // kick off first input chunk immediately
    issue_chunk(sm_in, gbase, 0, t);

    // stage small params while loads fly
    {
        float* sWpre = (float*)sWpre4;
        for (int idx = t; idx < 2048; idx += TPB) {
            int q = idx >> 9;
            int c = idx & 511;
            sWpre[c * 4 + q] = Wpre[idx];    // transpose -> [col][q]
        }
        if (t < 4)  sBpre[t] = bpre[t];
        if (t < 24) {
            float a = 0.5f * qparams[t];
            sQc[t] = cosf(a);
            sQs[t] = sinf(a);
        }
    }

    // ---- pre-GEMM: double-buffered chunk pipeline ----
    float ax = 0.f, ay = 0.f, az = 0.f, aw = 0.f;
#pragma unroll 2
    for (int ct = 0; ct < NCH; ct++) {
        float* cur = sm_in + (ct & 1) * TILE_F;
        if (ct + 1 < NCH) {
            issue_chunk(sm_in + ((ct + 1) & 1) * TILE_F, gbase, ct + 1, t);
            asm volatile("cp.async.wait_group 1;\n");
        } else {
            asm volatile("cp.async.wait_group 0;\n");
        }
        __syncthreads();   // chunk ct visible to all (also covers weight staging at ct=0)

        const float4* xrow = (const float4*)(cur + t * RSTR);   // conflict-free: 144B stride
#pragma unroll
        for (int j4 = 0; j4 < 8; j4++) {
            float4 x  = xrow[j4];
            int c = ct * CCH + j4 * 4;
            float4 w0 = sWpre4[c + 0];
            float4 w1 = sWpre4[c + 1];
            float4 w2 = sWpre4[c + 2];
            float4 w3 = sWpre4[c + 3];
            ax += x.x * w0.x + x.y * w1.x + x.z * w2.x + x.w * w3.x;
            ay += x.x * w0.y + x.y * w1.y + x.z * w2.y + x.w * w3.y;
            az += x.x * w0.z + x.y * w1.z + x.z * w2.z + x.w * w3.z;
            aw += x.x * w0.w + x.y * w1.w + x.z * w2.w + x.w * w3.w;
        }
        __syncthreads();   // everyone done with buffer before it is overwritten
    }

    // ---- activation + circuit (one sample per thread, state in registers) ----
    const float QPI4 = 0.78539816339744830962f;   // pi/4 (half of pi/2 gate angle)
    float c0, s0, c1, s1, c2, s2, c3, s3;
    sincosf(tanhf(ax + sBpre[0]) * QPI4, &s0, &c0);
    sincosf(tanhf(ay + sBpre[1]) * QPI4, &s1, &c1);
    sincosf(tanhf(az + sBpre[2]) * QPI4, &s2, &c2);
    sincosf(tanhf(aw + sBpre[3]) * QPI4, &s3, &c3);

    float st[16];
#pragma unroll
    for (int i = 0; i < 16; i++) st[i] = 0.25f;

    ry_gate<8>(st, c0, s0);
    ry_gate<4>(st, c1, s1);
    ry_gate<2>(st, c2, s2);
    ry_gate<1>(st, c3, s3);

#pragma unroll
    for (int k = 0; k < 6; k++) {
        // CNOT(0,1), CNOT(2,3), CNOT(1,2)
        swp(st[8], st[12]); swp(st[9], st[13]); swp(st[10], st[14]); swp(st[11], st[15]);
        swp(st[2], st[3]);  swp(st[6], st[7]);  swp(st[10], st[11]); swp(st[14], st[15]);
        swp(st[4], st[6]);  swp(st[5], st[7]);  swp(st[12], st[14]); swp(st[13], st[15]);
        ry_gate<8>(st, sQc[4 * k + 0], sQs[4 * k + 0]);
        ry_gate<4>(st, sQc[4 * k + 1], sQs[4 * k + 1]);
        ry_gate<2>(st, sQc[4 * k + 2], sQs[4 * k + 2]);
        ry_gate<1>(st, sQc[4 * k + 3], sQs[4 * k + 3]);
    }

    float z0 = 0.f, z1 = 0.f, z2 = 0.f, z3 = 0.f;
#pragma unroll
    for (int i = 0; i < 16; i++) {
        float p = st[i] * st[i];
        z0 += (i & 8) ? -p : p;
        z1 += (i & 4) ? -p : p;
        z2 += (i & 2) ? -p : p;
        z3 += (i & 1) ? -p : p;
    }

    szl4[t] = make_float4(z0, z1, z2, z3);
    __syncthreads();

    // ---- warp-cooperative coalesced epilogue ----
    // lane l owns output float4 columns l and 32+l (l<18); weights in registers.
    const int lane = t & 31;
    const int wrp  = t >> 5;
    const float4* wp4 = (const float4*)Wpost;   // row c of W_post = one float4
    const float4* bp4 = (const float4*)bpost;

    float4 wa0 = wp4[4 * lane + 0];
    float4 wa1 = wp4[4 * lane + 1];
    float4 wa2 = wp4[4 * lane + 2];
    float4 wa3 = wp4[4 * lane + 3];
    float4 ba  = bp4[lane];

    const bool hasB = (lane < 18);
    const int cb = 32 + lane;
    float4 wb0, wb1, wb2, wb3, bb;
    if (hasB) {
        wb0 = wp4[4 * cb + 0];
        wb1 = wp4[4 * cb + 1];
        wb2 = wp4[4 * cb + 2];
        wb3 = wp4[4 * cb + 3];
        bb  = bp4[cb];
    }

    const int rbase = wrp * 32;
#pragma unroll 4
    for (int r = 0; r < 32; r++) {
        int row = rbase + r;
        float4 zv = szl4[row];                       // broadcast LDS
        float4* orow = (float4*)(out + (size_t)(blockBase + row) * 200);
        float4 o;
        o.x = ba.x + zv.x * wa0.x + zv.y * wa0.y + zv.z * wa0.z + zv.w * wa0.w;
        o.y = ba.y + zv.x * wa1.x + zv.y * wa1.y + zv.z * wa1.z + zv.w * wa1.w;
        o.z = ba.z + zv.x * wa2.x + zv.y * wa2.y + zv.z * wa2.z + zv.w * wa2.w;
        o.w = ba.w + zv.x * wa3.x + zv.y * wa3.y + zv.z * wa3.z + zv.w * wa3.w;
        orow[lane] = o;                              // contiguous 512B per warp
        if (hasB) {
            float4 p;
            p.x = bb.x + zv.x * wb0.x + zv.y * wb0.y + zv.z * wb0.z + zv.w * wb0.w;
            p.y = bb.y + zv.x * wb1.x + zv.y * wb1.y + zv.z * wb1.z + zv.w * wb1.w;
            p.z = bb.z + zv.x * wb2.x + zv.y * wb2.y + zv.z * wb2.z + zv.w * wb2.w;
            p.w = bb.w + zv.x * wb3.x + zv.y * wb3.y + zv.z * wb3.z + zv.w * wb3.w;
            orow[cb] = p;
        }
    }
}

extern "C" void kernel_launch(void* const* d_in, const int* in_sizes, int n_in,
                              void* d_out, int out_size)
{
    const float* input   = (const float*)d_in[0];  // [65536,512]
    const float* Wpre    = (const float*)d_in[1];  // [4,512]
    const float* bpre    = (const float*)d_in[2];  // [4]
    const float* qparams = (const float*)d_in[3];  // [24]
    const float* Wpost   = (const float*)d_in[4];  // [200,4]
    const float* bpost   = (const float*)d_in[5];  // [200]
    float* out = (float*)d_out;                    // [65536,200]

    cudaFuncSetAttribute(dqn_fused_kernel,
                         cudaFuncAttributeMaxDynamicSharedMemorySize, SMEM_BYTES);
    dqn_fused_kernel<<<NBLK, TPB, SMEM_BYTES>>>(input, Wpre, bpre, qparams,
                                                Wpost, bpost, out);
}

// round 3
// speedup vs baseline: 1.6652x; 1.0831x over previous
#include <cuda_runtime.h>
#include <cuda_bf16.h>

#define TPB 128
#define SPB 128            // samples per block (32 per warp)
#define NBLK 512           // 65536 / 128

template<int STRIDE>
__device__ __forceinline__ void ry_gate(float st[16], float c, float s) {
#pragma unroll
    for (int i = 0; i < 16; i++) {
        if ((i & STRIDE) == 0) {
            float a = st[i];
            float b = st[i | STRIDE];
            st[i]          = c * a - s * b;
            st[i | STRIDE] = s * a + c * b;
        }
    }
}

__device__ __forceinline__ void swp(float &a, float &b) { float t = a; a = b; b = t; }

__global__ __launch_bounds__(TPB, 5)
void dqn_fused_kernel(const float* __restrict__ input,   // [65536, 512]
                      const float* __restrict__ Wpre,    // [4, 512]
                      const float* __restrict__ bpre,    // [4]
                      const float* __restrict__ qparams, // [24]
                      const float* __restrict__ Wpost,   // [200, 4]
                      const float* __restrict__ bpost,   // [200]
                      float* __restrict__ out)           // [65536, 200]
{
    __shared__ float4 sWt[512];     // Wt[c] = {W[0][c],W[1][c],W[2][c],W[3][c]}
    __shared__ float4 szl[SPB];     // per-sample z
    __shared__ float  sQc[24], sQs[24], sBpre[4];

    const int t = threadIdx.x;

    // ---- stage transposed W_pre + small params (one-time, tiny) ----
    for (int c = t; c < 512; c += TPB)
        sWt[c] = make_float4(Wpre[c], Wpre[512 + c], Wpre[1024 + c], Wpre[1536 + c]);
    if (t < 24) {
        float a = 0.5f * qparams[t];
        sQc[t] = cosf(a);
        sQs[t] = sinf(a);
    }
    if (t < 4) sBpre[t] = bpre[t];
    __syncthreads();   // the only block barrier

    const int lane = t & 31;
    const int wrp  = t >> 5;
    const int p    = lane & 7;     // column position within segment
    const int s    = lane >> 3;    // segment = row-within-group
    const int rowBase = blockIdx.x * SPB + wrp * 32;   // warp's first global row
    const float* xbase = input + (size_t)rowBase * 512;

    // ---- warp-cooperative pre-GEMM: zero smem for x, W reused across 8 k-groups ----
    float4 acc[8];
#pragma unroll
    for (int k = 0; k < 8; k++) acc[k] = make_float4(0.f, 0.f, 0.f, 0.f);

#pragma unroll 2
    for (int jj = 0; jj < 16; jj++) {
        const int c4 = p + 8 * jj;          // float4-of-columns index (0..127)
        float4 w0 = sWt[4 * c4 + 0];
        float4 w1 = sWt[4 * c4 + 1];
        float4 w2 = sWt[4 * c4 + 2];
        float4 w3 = sWt[4 * c4 + 3];
#pragma unroll
        for (int k = 0; k < 8; k++) {
            const int row = 4 * k + s;
            float4 x = __ldcs((const float4*)(xbase + (size_t)row * 512) + c4);
            acc[k].x += x.x * w0.x + x.y * w1.x + x.z * w2.x + x.w * w3.x;
            acc[k].y += x.x * w0.y + x.y * w1.y + x.z * w2.y + x.w * w3.y;
            acc[k].z += x.x * w0.z + x.y * w1.z + x.z * w2.z + x.w * w3.z;
            acc[k].w += x.x * w0.w + x.y * w1.w + x.z * w2.w + x.w * w3.w;
        }
    }

    // ---- segment reduction (8 lanes) : 3 bfly rounds, lane p==k keeps row 4p+s ----
    float4 r = make_float4(0.f, 0.f, 0.f, 0.f);
#pragma unroll
    for (int k = 0; k < 8; k++) {
        float4 a = acc[k];
#pragma unroll
        for (int m = 1; m <= 4; m <<= 1) {
            a.x += __shfl_xor_sync(0xffffffffu, a.x, m);
            a.y += __shfl_xor_sync(0xffffffffu, a.y, m);
            a.z += __shfl_xor_sync(0xffffffffu, a.z, m);
            a.w += __shfl_xor_sync(0xffffffffu, a.w, m);
        }
        if (p == k) r = a;
    }
    const int myRow = 4 * p + s;   // row (within warp) this lane now owns

    // ---- activation + quantum circuit (state in registers) ----
    const float QPI4 = 0.78539816339744830962f;   // pi/4 = half of pi/2 gate angle
    float c0, s0, c1, s1, c2, s2, c3, s3;
    sincosf(tanhf(r.x + sBpre[0]) * QPI4, &s0, &c0);
    sincosf(tanhf(r.y + sBpre[1]) * QPI4, &s1, &c1);
    sincosf(tanhf(r.z + sBpre[2]) * QPI4, &s2, &c2);
    sincosf(tanhf(r.w + sBpre[3]) * QPI4, &s3, &c3);

    float st[16];
#pragma unroll
    for (int i = 0; i < 16; i++) st[i] = 0.25f;

    ry_gate<8>(st, c0, s0);
    ry_gate<4>(st, c1, s1);
    ry_gate<2>(st, c2, s2);
    ry_gate<1>(st, c3, s3);

#pragma unroll
    for (int k = 0; k < 6; k++) {
        // CNOT(0,1), CNOT(2,3), CNOT(1,2)  (pure register permutations)
        swp(st[8], st[12]); swp(st[9], st[13]); swp(st[10], st[14]); swp(st[11], st[15]);
        swp(st[2], st[3]);  swp(st[6], st[7]);  swp(st[10], st[11]); swp(st[14], st[15]);
        swp(st[4], st[6]);  swp(st[5], st[7]);  swp(st[12], st[14]); swp(st[13], st[15]);
        ry_gate<8>(st, sQc[4 * k + 0], sQs[4 * k + 0]);
        ry_gate<4>(st, sQc[4 * k + 1], sQs[4 * k + 1]);
        ry_gate<2>(st, sQc[4 * k + 2], sQs[4 * k + 2]);
        ry_gate<1>(st, sQc[4 * k + 3], sQs[4 * k + 3]);
    }

    float z0 = 0.f, z1 = 0.f, z2 = 0.f, z3 = 0.f;
#pragma unroll
    for (int i = 0; i < 16; i++) {
        float pp = st[i] * st[i];
        z0 += (i & 8) ? -pp : pp;
        z1 += (i & 4) ? -pp : pp;
        z2 += (i & 2) ? -pp : pp;
        z3 += (i & 1) ? -pp : pp;
    }

    szl[wrp * 32 + myRow] = make_float4(z0, z1, z2, z3);
    __syncwarp();   // warp-local: each warp consumes only its own 32 entries

    // ---- warp-cooperative coalesced epilogue ----
    // lane owns output float4 columns {lane} and {32+lane | lane<18}
    const float4* wp4 = (const float4*)Wpost;   // row c of W_post = one float4
    const float4* bp4 = (const float4*)bpost;

    float4 wa0 = wp4[4 * lane + 0];
    float4 wa1 = wp4[4 * lane + 1];
    float4 wa2 = wp4[4 * lane + 2];
    float4 wa3 = wp4[4 * lane + 3];
    float4 ba  = bp4[lane];

    const bool hasB = (lane < 18);
    const int cb = 32 + lane;
    float4 wb0, wb1, wb2, wb3, bb;
    if (hasB) {
        wb0 = wp4[4 * cb + 0];
        wb1 = wp4[4 * cb + 1];
        wb2 = wp4[4 * cb + 2];
        wb3 = wp4[4 * cb + 3];
        bb  = bp4[cb];
    }

#pragma unroll 4
    for (int rr = 0; rr < 32; rr++) {
        float4 zv = szl[wrp * 32 + rr];                 // broadcast LDS
        float4* orow = (float4*)(out + (size_t)(rowBase + rr) * 200);
        float4 o;
        o.x = ba.x + zv.x * wa0.x + zv.y * wa0.y + zv.z * wa0.z + zv.w * wa0.w;
        o.y = ba.y + zv.x * wa1.x + zv.y * wa1.y + zv.z * wa1.z + zv.w * wa1.w;
        o.z = ba.z + zv.x * wa2.x + zv.y * wa2.y + zv.z * wa2.z + zv.w * wa2.w;
        o.w = ba.w + zv.x * wa3.x + zv.y * wa3.y + zv.z * wa3.z + zv.w * wa3.w;
        __stcs(orow + lane, o);                         // contiguous 512B per warp
        if (hasB) {
            float4 q;
            q.x = bb.x + zv.x * wb0.x + zv.y * wb0.y + zv.z * wb0.z + zv.w * wb0.w;
            q.y = bb.y + zv.x * wb1.x + zv.y * wb1.y + zv.z * wb1.z + zv.w * wb1.w;
            q.z = bb.z + zv.x * wb2.x + zv.y * wb2.y + zv.z * wb2.z + zv.w * wb2.w;
            q.w = bb.w + zv.x * wb3.x + zv.y * wb3.y + zv.z * wb3.z + zv.w * wb3.w;
            __stcs(orow + cb, q);
        }
    }
}

extern "C" void kernel_launch(void* const* d_in, const int* in_sizes, int n_in,
                              void* d_out, int out_size)
{
    const float* input   = (const float*)d_in[0];  // [65536,512]
    const float* Wpre    = (const float*)d_in[1];  // [4,512]
    const float* bpre    = (const float*)d_in[2];  // [4]
    const float* qparams = (const float*)d_in[3];  // [24]
    const float* Wpost   = (const float*)d_in[4];  // [200,4]
    const float* bpost   = (const float*)d_in[5];  // [200]
    float* out = (float*)d_out;                    // [65536,200]

    dqn_fused_kernel<<<NBLK, TPB>>>(input, Wpre, bpre, qparams, Wpost, bpost, out);
}